// round 8
// baseline (speedup 1.0000x reference)
#include <cuda_runtime.h>
#include <cstdint>

// 2-layer LSTM (B=4096,T=256,D=4,H=64)+FC, fp32. Crossbar-balanced tile:
// 128 thr/CTA, thread = 8 gate-rows (2 units x 4 gates) x 8 elems.
// v K-major [k][32e] (128B rows): accumulators pack ELEM pairs -> each 16B
// v-load feeds 2 f32x2 operands; w scalar splat. LDS phases/step == FFMA2
// cycles/step == 8192 (was 16384 vs 8192). One barrier/step.

#define TT 256
#define V_OFF 131072
#define VBUF  16384
#define SM_TOTAL 163840

typedef unsigned long long u64;
__device__ float g_h1[(size_t)128 * TT * 2048];   // [blk][t][j64][e32]

static __device__ __forceinline__ u64 pkss(float f){u64 r;asm("mov.b64 %0,{%1,%1};":"=l"(r):"f"(f));return r;}
static __device__ __forceinline__ void up2(u64 v,float&a,float&b){asm("mov.b64 {%0,%1},%2;":"=f"(a),"=f"(b):"l"(v));}
static __device__ __forceinline__ u64 f2(u64 a,u64 b,u64 c){u64 d;asm("fma.rn.f32x2 %0,%1,%2,%3;":"=l"(d):"l"(a),"l"(b),"l"(c));return d;}
static __device__ __forceinline__ float tanha(float x){float r;asm("tanh.approx.f32 %0,%1;":"=f"(r):"f"(x));return r;}
static __device__ __forceinline__ float sigt(float x){return fmaf(0.5f,tanha(0.5f*x),0.5f);}
static __device__ __forceinline__ uint32_t s2u(const void*p){uint32_t a;
    asm("{.reg .u64 t;cvta.to.shared.u64 t,%1;cvt.u32.u64 %0,t;}":"=r"(a):"l"(p));return a;}

#define XL2(d0,d1,IMM) asm volatile("ld.shared.v2.u64 {%0,%1},[%2+%3];" \
    :"=l"(d0),"=l"(d1):"r"(xb),"n"(IMM))
#define STS4(A,IMM,V) asm volatile("st.shared.v4.f32 [%0+%1],{%2,%3,%4,%5};" \
    ::"r"(A),"n"(IMM),"f"((V).x),"f"((V).y),"f"((V).z),"f"((V).w))
#define STS1(A,IMM,V) asm volatile("st.shared.f32 [%0+%1],%2;"::"r"(A),"n"(IMM),"f"(V))

// slot S = unit(S>>2)*?  row(S,gg) = (S&3)*64 + 2*gg + (S>>2); w smem [kc][S][gg]
#define SLOT(KC,S) do{ float q0,q1,q2,q3;u64 ws; \
  asm volatile("ld.shared.v4.f32 {%0,%1,%2,%3},[%4+%5];" \
    :"=f"(q0),"=f"(q1),"=f"(q2),"=f"(q3):"r"(wb),"n"((KC)*4096+(S)*512)); \
  ws=pkss(q0);acc[S][0]=f2(ws,x00,acc[S][0]);acc[S][1]=f2(ws,x01,acc[S][1]); \
              acc[S][2]=f2(ws,x02,acc[S][2]);acc[S][3]=f2(ws,x03,acc[S][3]); \
  ws=pkss(q1);acc[S][0]=f2(ws,x10,acc[S][0]);acc[S][1]=f2(ws,x11,acc[S][1]); \
              acc[S][2]=f2(ws,x12,acc[S][2]);acc[S][3]=f2(ws,x13,acc[S][3]); \
  ws=pkss(q2);acc[S][0]=f2(ws,x20,acc[S][0]);acc[S][1]=f2(ws,x21,acc[S][1]); \
              acc[S][2]=f2(ws,x22,acc[S][2]);acc[S][3]=f2(ws,x23,acc[S][3]); \
  ws=pkss(q3);acc[S][0]=f2(ws,x30,acc[S][0]);acc[S][1]=f2(ws,x31,acc[S][1]); \
              acc[S][2]=f2(ws,x32,acc[S][2]);acc[S][3]=f2(ws,x33,acc[S][3]); \
}while(0)

#define CHUNK(KC) do{ \
  u64 x00,x01,x02,x03,x10,x11,x12,x13,x20,x21,x22,x23,x30,x31,x32,x33; \
  XL2(x00,x01,(KC)*512+0);  XL2(x02,x03,(KC)*512+16); \
  XL2(x10,x11,(KC)*512+128);XL2(x12,x13,(KC)*512+144); \
  XL2(x20,x21,(KC)*512+256);XL2(x22,x23,(KC)*512+272); \
  XL2(x30,x31,(KC)*512+384);XL2(x32,x33,(KC)*512+400); \
  SLOT(KC,0);SLOT(KC,1);SLOT(KC,2);SLOT(KC,3); \
  SLOT(KC,4);SLOT(KC,5);SLOT(KC,6);SLOT(KC,7); \
}while(0)

#define G8 do{CHUNK(0);CHUNK(1);CHUNK(2);CHUNK(3);CHUNK(4);CHUNK(5);CHUNK(6);CHUNK(7);}while(0)

#define UPD(U) do{ _Pragma("unroll") for(int p=0;p<4;p++){ \
  float i0,i1,f0,f1,g0,g1,o0,o1; \
  up2(acc[4*(U)][p],i0,i1);  up2(acc[4*(U)+1][p],f0,f1); \
  up2(acc[4*(U)+2][p],g0,g1);up2(acc[4*(U)+3][p],o0,o1); \
  cc[U][2*p]  =sigt(f0)*cc[U][2*p]  +sigt(i0)*tanha(g0); \
  cc[U][2*p+1]=sigt(f1)*cc[U][2*p+1]+sigt(i1)*tanha(g1); \
  hv[U][2*p]  =sigt(o0)*tanha(cc[U][2*p]); \
  hv[U][2*p+1]=sigt(o1)*tanha(cc[U][2*p+1]); }}while(0)

// ---------------------------------------------------------------------------
__global__ void __launch_bounds__(128,1) lstm_l1(
    const float* __restrict__ Wih,const float* __restrict__ Whh,
    const float* __restrict__ bih,const float* __restrict__ bhh,
    const float* __restrict__ Wfc,const float* __restrict__ bfc,
    float* __restrict__ out)
{
    extern __shared__ char sm[];
    const int tid=threadIdx.x, eg=tid&3, gg=tid>>2;
    const int b0=blockIdx.x*32;

    for(int idx=tid;idx<8192;idx+=128){            // weights [kc32][s8][gg32]
        int kc=idx>>8,s=(idx>>5)&7,g=idx&31;
        int r=(s&3)*64+2*g+(s>>2), k=kc*4;
        const float* src = (k<64)? Wih+r*64+k : Whh+r*64+(k-64);
        *(float4*)(sm+kc*4096+s*512+g*16)=*(const float4*)src;
    }

    const uint32_t smb=s2u(sm);
    const uint32_t wb0=smb+gg*16;
    uint32_t xrd=smb+V_OFF+eg*32;
    uint32_t hs=smb+V_OFF+VBUF+(64+2*gg)*128+eg*32;
    uint32_t ps=smb+V_OFF+VBUF+(2*gg)*128+eg*32;

    const float* h1p=g_h1+(size_t)blockIdx.x*TT*2048+2*gg*32+eg*8;
    {   // init V0: rows 0..63 <- h1[t=0]; rows 64..127 <- 0
        float4 a=*(const float4*)(h1p), b4=*(const float4*)(h1p+4);
        float4 c4=*(const float4*)(h1p+32), d4=*(const float4*)(h1p+36);
        uint32_t vi=smb+V_OFF+2*gg*128+eg*32;
        STS4(vi,0,a);STS4(vi,16,b4);STS4(vi,128,c4);STS4(vi,144,d4);
        float4 z=make_float4(0.f,0.f,0.f,0.f);
        STS4(vi,8192,z);STS4(vi,8208,z);STS4(vi,8320,z);STS4(vi,8336,z);
    }
    h1p+=2048;

    float bias[8];
#pragma unroll
    for(int s=0;s<8;s++){int r=(s&3)*64+2*gg+(s>>2);bias[s]=bih[r]+bhh[r];}
    float cc[2][8], hv[2][8];
#pragma unroll
    for(int u=0;u<2;u++)
#pragma unroll
        for(int e=0;e<8;e++)cc[u][e]=0.f;
    int xf=VBUF,hf=-VBUF;
    __syncthreads();

    for(int s=0;s<TT;s++){
        float4 p00,p01,p10,p11;
        if(s+1<TT){p00=*(const float4*)(h1p);   p01=*(const float4*)(h1p+4);
                   p10=*(const float4*)(h1p+32);p11=*(const float4*)(h1p+36);}
        else {p00=p01=p10=p11=make_float4(0.f,0.f,0.f,0.f);}
        h1p+=2048;

        u64 acc[8][4];
#pragma unroll
        for(int q=0;q<8;q++){u64 bp=pkss(bias[q]);
            acc[q][0]=bp;acc[q][1]=bp;acc[q][2]=bp;acc[q][3]=bp;}
        uint32_t xb=xrd, wb=wb0;
        G8; xb+=4096; wb+=32768;
        G8; xb+=4096; wb+=32768;
        G8; xb+=4096; wb+=32768;
        G8;

        UPD(0);UPD(1);
        float4 t;
        t=make_float4(hv[0][0],hv[0][1],hv[0][2],hv[0][3]);STS4(hs,0,t);
        t=make_float4(hv[0][4],hv[0][5],hv[0][6],hv[0][7]);STS4(hs,16,t);
        t=make_float4(hv[1][0],hv[1][1],hv[1][2],hv[1][3]);STS4(hs,128,t);
        t=make_float4(hv[1][4],hv[1][5],hv[1][6],hv[1][7]);STS4(hs,144,t);
        STS4(ps,0,p00);STS4(ps,16,p01);STS4(ps,128,p10);STS4(ps,144,p11);
        __syncthreads();
        xrd+=xf;xf=-xf; hs+=hf;ps+=hf;hf=-hf;
    }

    // fused FC: partials over (unit pair) -> smem -> 32-thread reduce
    {
        float wa=Wfc[2*gg], wbv=Wfc[2*gg+1];
        float pp[8];
#pragma unroll
        for(int e=0;e<8;e++)pp[e]=hv[0][e]*wa+hv[1][e]*wbv;
        uint32_t pb=smb+V_OFF+gg*128+eg*32;
        float4 t=make_float4(pp[0],pp[1],pp[2],pp[3]);STS4(pb,0,t);
        t=make_float4(pp[4],pp[5],pp[6],pp[7]);STS4(pb,16,t);
        __syncthreads();
        if(tid<32){
            float v=bfc[0];
#pragma unroll
            for(int g=0;g<32;g++) v+=*(const float*)(sm+V_OFF+g*128+tid*4);
            out[b0+tid]=v;
        }
    }
}

// ---------------------------------------------------------------------------
// Layer 0: v rows 0..3 = x (chunk 0, Wih0), rows 4..67 = h (chunks 1..16).
__global__ void __launch_bounds__(128,1) lstm_l0(
    const float* __restrict__ x,const float* __restrict__ Wih,
    const float* __restrict__ Whh,const float* __restrict__ bih,
    const float* __restrict__ bhh)
{
    extern __shared__ char sm[];
    const int tid=threadIdx.x, eg=tid&3, gg=tid>>2;
    const int b0=blockIdx.x*32;

    for(int idx=tid;idx<4352;idx+=128){            // weights [kc17][s8][gg32]
        int kc=idx>>8,s=(idx>>5)&7,g=idx&31;
        int r=(s&3)*64+2*g+(s>>2);
        const float* src = (kc==0)? Wih+r*4 : Whh+r*64+(kc-1)*4;
        *(float4*)(sm+kc*4096+s*512+g*16)=*(const float4*)src;
    }

    const uint32_t smb=s2u(sm);
    const uint32_t wb0=smb+gg*16;
    uint32_t xrd=smb+V_OFF+eg*32;
    uint32_t hs=smb+V_OFF+VBUF+(4+2*gg)*128+eg*32;
    uint32_t xs=smb+V_OFF+VBUF+tid*4;
    {   // init V0: h rows zero; x(0) transposed into rows 0..3
        float4 z=make_float4(0.f,0.f,0.f,0.f);
        uint32_t vi=smb+V_OFF+(4+2*gg)*128+eg*32;
        STS4(vi,0,z);STS4(vi,16,z);STS4(vi,128,z);STS4(vi,144,z);
    }
    const float* xp=0;
    if(tid<32){
        xp=x+(size_t)(b0+tid)*TT*4;
        float4 x0=*(const float4*)xp;
        uint32_t xi=smb+V_OFF+tid*4;
        STS1(xi,0,x0.x);STS1(xi,128,x0.y);STS1(xi,256,x0.z);STS1(xi,384,x0.w);
    }
    float* gp=g_h1+(size_t)blockIdx.x*TT*2048+2*gg*32+eg*8;

    float bias[8];
#pragma unroll
    for(int s=0;s<8;s++){int r=(s&3)*64+2*gg+(s>>2);bias[s]=bih[r]+bhh[r];}
    float cc[2][8], hv[2][8];
#pragma unroll
    for(int u=0;u<2;u++)
#pragma unroll
        for(int e=0;e<8;e++)cc[u][e]=0.f;
    int xf=VBUF,hf=-VBUF;
    __syncthreads();

    for(int s=0;s<TT;s++){
        float4 px=make_float4(0.f,0.f,0.f,0.f);
        if(tid<32&&s+1<TT)px=*(const float4*)(xp+(size_t)(s+1)*4);

        u64 acc[8][4];
#pragma unroll
        for(int q=0;q<8;q++){u64 bp=pkss(bias[q]);
            acc[q][0]=bp;acc[q][1]=bp;acc[q][2]=bp;acc[q][3]=bp;}
        uint32_t xb=xrd, wb=wb0;
        G8; xb+=4096; wb+=32768;
        G8; xb+=4096; wb+=32768;
        CHUNK(0);                                  // chunk 16 (rows 64..67)

        UPD(0);UPD(1);
        float4 t;
        t=make_float4(hv[0][0],hv[0][1],hv[0][2],hv[0][3]);STS4(hs,0,t);  *(float4*)(gp)   =t;
        t=make_float4(hv[0][4],hv[0][5],hv[0][6],hv[0][7]);STS4(hs,16,t); *(float4*)(gp+4) =t;
        t=make_float4(hv[1][0],hv[1][1],hv[1][2],hv[1][3]);STS4(hs,128,t);*(float4*)(gp+32)=t;
        t=make_float4(hv[1][4],hv[1][5],hv[1][6],hv[1][7]);STS4(hs,144,t);*(float4*)(gp+36)=t;
        gp+=2048;
        if(tid<32){STS1(xs,0,px.x);STS1(xs,128,px.y);STS1(xs,256,px.z);STS1(xs,384,px.w);}
        __syncthreads();
        xrd+=xf;xf=-xf; hs+=hf;xs+=hf;hf=-hf;
    }
}

// ---------------------------------------------------------------------------
extern "C" void kernel_launch(void* const* d_in, const int* in_sizes, int n_in,
                              void* d_out, int out_size)
{
    const float* x    =(const float*)d_in[0];
    const float* Wih0 =(const float*)d_in[1];
    const float* Whh0 =(const float*)d_in[2];
    const float* bih0 =(const float*)d_in[3];
    const float* bhh0 =(const float*)d_in[4];
    const float* Wih1 =(const float*)d_in[5];
    const float* Whh1 =(const float*)d_in[6];
    const float* bih1 =(const float*)d_in[7];
    const float* bhh1 =(const float*)d_in[8];
    const float* Wfc  =(const float*)d_in[9];
    const float* bfc  =(const float*)d_in[10];
    float* out=(float*)d_out;

    cudaFuncSetAttribute(lstm_l0,cudaFuncAttributeMaxDynamicSharedMemorySize,SM_TOTAL);
    cudaFuncSetAttribute(lstm_l1,cudaFuncAttributeMaxDynamicSharedMemorySize,SM_TOTAL);
    lstm_l0<<<128,128,SM_TOTAL>>>(x,Wih0,Whh0,bih0,bhh0);
    lstm_l1<<<128,128,SM_TOTAL>>>(Wih1,Whh1,bih1,bhh1,Wfc,bfc,out);
}

// round 9
// speedup vs baseline: 1.1898x; 1.1898x over previous
#include <cuda_runtime.h>
#include <cstdint>

// 2-layer LSTM (B=4096,T=256,D=4,H=64)+FC, fp32. Crossbar-balanced 8gx8e
// tile (R8) + hand software-pipelined operand loads:
//   - weight vec4 for slot S+1 prefetched (alternating p/q reg sets) before
//     slot S's 16 FFMA2 -> >=32cyc load->use distance (lat 29 hidden)
//   - x (v) loads at chunk top, ~10cyc residual boundary stall
//   - runtime chunk loop (unroll 4), body ~3KB -> fits I$
// volatile asm pins this schedule; pure ops non-volatile for ptxas polish.

#define TT 256
#define V_OFF 131072
#define VBUF  16384
#define SM_TOTAL 163840

typedef unsigned long long u64;
__device__ float g_h1[(size_t)128 * TT * 2048];   // [blk][t][j64][e32]

static __device__ __forceinline__ u64 pkss(float f){u64 r;asm("mov.b64 %0,{%1,%1};":"=l"(r):"f"(f));return r;}
static __device__ __forceinline__ void up2(u64 v,float&a,float&b){asm("mov.b64 {%0,%1},%2;":"=f"(a),"=f"(b):"l"(v));}
static __device__ __forceinline__ u64 f2(u64 a,u64 b,u64 c){u64 d;asm("fma.rn.f32x2 %0,%1,%2,%3;":"=l"(d):"l"(a),"l"(b),"l"(c));return d;}
static __device__ __forceinline__ float tanha(float x){float r;asm("tanh.approx.f32 %0,%1;":"=f"(r):"f"(x));return r;}
static __device__ __forceinline__ float sigt(float x){return fmaf(0.5f,tanha(0.5f*x),0.5f);}
static __device__ __forceinline__ uint32_t s2u(const void*p){uint32_t a;
    asm("{.reg .u64 t;cvta.to.shared.u64 t,%1;cvt.u32.u64 %0,t;}":"=r"(a):"l"(p));return a;}

#define XL2(d0,d1,IMM) asm volatile("ld.shared.v2.u64 {%0,%1},[%2+%3];" \
    :"=l"(d0),"=l"(d1):"r"(xb),"n"(IMM))
#define STS4(A,IMM,V) asm volatile("st.shared.v4.f32 [%0+%1],{%2,%3,%4,%5};" \
    ::"r"(A),"n"(IMM),"f"((V).x),"f"((V).y),"f"((V).z),"f"((V).w))
#define STS1(A,IMM,V) asm volatile("st.shared.f32 [%0+%1],%2;"::"r"(A),"n"(IMM),"f"(V))

#define WLOADP(IMM) asm volatile("ld.shared.v4.f32 {%0,%1,%2,%3},[%4+%5];" \
    :"=f"(p0),"=f"(p1),"=f"(p2),"=f"(p3):"r"(wb),"n"(IMM))
#define WLOADQ(IMM) asm volatile("ld.shared.v4.f32 {%0,%1,%2,%3},[%4+%5];" \
    :"=f"(q0),"=f"(q1),"=f"(q2),"=f"(q3):"r"(wb),"n"(IMM))

// 16 FFMA2 for slot S using preloaded scalar set W (W##0..W##3)
#define SLOTF(S,W) do{ u64 ws; \
  ws=pkss(W##0);acc[S][0]=f2(ws,x00,acc[S][0]);acc[S][1]=f2(ws,x01,acc[S][1]); \
               acc[S][2]=f2(ws,x02,acc[S][2]);acc[S][3]=f2(ws,x03,acc[S][3]); \
  ws=pkss(W##1);acc[S][0]=f2(ws,x10,acc[S][0]);acc[S][1]=f2(ws,x11,acc[S][1]); \
               acc[S][2]=f2(ws,x12,acc[S][2]);acc[S][3]=f2(ws,x13,acc[S][3]); \
  ws=pkss(W##2);acc[S][0]=f2(ws,x20,acc[S][0]);acc[S][1]=f2(ws,x21,acc[S][1]); \
               acc[S][2]=f2(ws,x22,acc[S][2]);acc[S][3]=f2(ws,x23,acc[S][3]); \
  ws=pkss(W##3);acc[S][0]=f2(ws,x30,acc[S][0]);acc[S][1]=f2(ws,x31,acc[S][1]); \
               acc[S][2]=f2(ws,x32,acc[S][2]);acc[S][3]=f2(ws,x33,acc[S][3]); \
}while(0)

// one chunk (4 k-values): x loads up front; w slot S+1 prefetched before
// slot S's FMAs (p/q alternate; slot7 prefetches next chunk's slot0 -> p)
#define PCHUNK do{ \
  u64 x00,x01,x02,x03,x10,x11,x12,x13,x20,x21,x22,x23,x30,x31,x32,x33; \
  XL2(x00,x01,0);  XL2(x02,x03,16); XL2(x10,x11,128);XL2(x12,x13,144); \
  XL2(x20,x21,256);XL2(x22,x23,272);XL2(x30,x31,384);XL2(x32,x33,400); \
  WLOADQ(512);  SLOTF(0,p); \
  WLOADP(1024); SLOTF(1,q); \
  WLOADQ(1536); SLOTF(2,p); \
  WLOADP(2048); SLOTF(3,q); \
  WLOADQ(2560); SLOTF(4,p); \
  WLOADP(3072); SLOTF(5,q); \
  WLOADQ(3584); SLOTF(6,p); \
  WLOADP(4096); SLOTF(7,q); \
  wb+=4096; xb+=512; \
}while(0)

#define UPD(U) do{ _Pragma("unroll") for(int p_=0;p_<4;p_++){ \
  float i0,i1,f0,f1,g0,g1,o0,o1; \
  up2(acc[4*(U)][p_],i0,i1);  up2(acc[4*(U)+1][p_],f0,f1); \
  up2(acc[4*(U)+2][p_],g0,g1);up2(acc[4*(U)+3][p_],o0,o1); \
  cc[U][2*p_]  =sigt(f0)*cc[U][2*p_]  +sigt(i0)*tanha(g0); \
  cc[U][2*p_+1]=sigt(f1)*cc[U][2*p_+1]+sigt(i1)*tanha(g1); \
  hv[U][2*p_]  =sigt(o0)*tanha(cc[U][2*p_]); \
  hv[U][2*p_+1]=sigt(o1)*tanha(cc[U][2*p_+1]); }}while(0)

// ---------------------------------------------------------------------------
__global__ void __launch_bounds__(128,1) lstm_l1(
    const float* __restrict__ Wih,const float* __restrict__ Whh,
    const float* __restrict__ bih,const float* __restrict__ bhh,
    const float* __restrict__ Wfc,const float* __restrict__ bfc,
    float* __restrict__ out)
{
    extern __shared__ char sm[];
    const int tid=threadIdx.x, eg=tid&3, gg=tid>>2;
    const int b0=blockIdx.x*32;

    for(int idx=tid;idx<8192;idx+=128){            // weights [kc32][s8][gg32]
        int kc=idx>>8,s=(idx>>5)&7,g=idx&31;
        int r=(s&3)*64+2*g+(s>>2), k=kc*4;
        const float* src = (k<64)? Wih+r*64+k : Whh+r*64+(k-64);
        *(float4*)(sm+kc*4096+s*512+g*16)=*(const float4*)src;
    }

    const uint32_t smb=s2u(sm);
    const uint32_t wb0=smb+gg*16;
    uint32_t xrd=smb+V_OFF+eg*32;
    uint32_t hs=smb+V_OFF+VBUF+(64+2*gg)*128+eg*32;
    uint32_t ps=smb+V_OFF+VBUF+(2*gg)*128+eg*32;

    const float* h1p=g_h1+(size_t)blockIdx.x*TT*2048+2*gg*32+eg*8;
    {   // init V0: rows 0..63 <- h1[t=0]; rows 64..127 <- 0
        float4 a=*(const float4*)(h1p), b4=*(const float4*)(h1p+4);
        float4 c4=*(const float4*)(h1p+32), d4=*(const float4*)(h1p+36);
        uint32_t vi=smb+V_OFF+2*gg*128+eg*32;
        STS4(vi,0,a);STS4(vi,16,b4);STS4(vi,128,c4);STS4(vi,144,d4);
        float4 z=make_float4(0.f,0.f,0.f,0.f);
        STS4(vi,8192,z);STS4(vi,8208,z);STS4(vi,8320,z);STS4(vi,8336,z);
    }
    h1p+=2048;

    float bias[8];
#pragma unroll
    for(int s=0;s<8;s++){int r=(s&3)*64+2*gg+(s>>2);bias[s]=bih[r]+bhh[r];}
    float cc[2][8], hv[2][8];
#pragma unroll
    for(int u=0;u<2;u++)
#pragma unroll
        for(int e=0;e<8;e++)cc[u][e]=0.f;
    int xf=VBUF,hf=-VBUF;
    __syncthreads();

    for(int s=0;s<TT;s++){
        float4 p00,p01,p10,p11;
        if(s+1<TT){p00=*(const float4*)(h1p);   p01=*(const float4*)(h1p+4);
                   p10=*(const float4*)(h1p+32);p11=*(const float4*)(h1p+36);}
        else {p00=p01=p10=p11=make_float4(0.f,0.f,0.f,0.f);}
        h1p+=2048;

        u64 acc[8][4];
#pragma unroll
        for(int q=0;q<8;q++){u64 bp=pkss(bias[q]);
            acc[q][0]=bp;acc[q][1]=bp;acc[q][2]=bp;acc[q][3]=bp;}

        float p0,p1,p2,p3,q0,q1,q2,q3;
        uint32_t xb=xrd, wb=wb0;
        WLOADP(0);                                  // prologue: slot0 of chunk0
#pragma unroll 4
        for(int kc=0;kc<32;kc++) PCHUNK;

        UPD(0);UPD(1);
        float4 t;
        t=make_float4(hv[0][0],hv[0][1],hv[0][2],hv[0][3]);STS4(hs,0,t);
        t=make_float4(hv[0][4],hv[0][5],hv[0][6],hv[0][7]);STS4(hs,16,t);
        t=make_float4(hv[1][0],hv[1][1],hv[1][2],hv[1][3]);STS4(hs,128,t);
        t=make_float4(hv[1][4],hv[1][5],hv[1][6],hv[1][7]);STS4(hs,144,t);
        STS4(ps,0,p00);STS4(ps,16,p01);STS4(ps,128,p10);STS4(ps,144,p11);
        __syncthreads();
        xrd+=xf;xf=-xf; hs+=hf;ps+=hf;hf=-hf;
    }

    // fused FC: per-thread partial over its 2 units x 8 elems -> smem -> reduce
    {
        float wa=Wfc[2*gg], wbv=Wfc[2*gg+1];
        float pp[8];
#pragma unroll
        for(int e=0;e<8;e++)pp[e]=hv[0][e]*wa+hv[1][e]*wbv;
        uint32_t pb=smb+V_OFF+gg*128+eg*32;
        float4 t=make_float4(pp[0],pp[1],pp[2],pp[3]);STS4(pb,0,t);
        t=make_float4(pp[4],pp[5],pp[6],pp[7]);STS4(pb,16,t);
        __syncthreads();
        if(tid<32){
            float v=bfc[0];
#pragma unroll
            for(int g=0;g<32;g++) v+=*(const float*)(sm+V_OFF+g*128+tid*4);
            out[b0+tid]=v;
        }
    }
}

// ---------------------------------------------------------------------------
// Layer 0: v rows 0..3 = x (chunk 0, Wih0), rows 4..67 = h (chunks 1..16).
__global__ void __launch_bounds__(128,1) lstm_l0(
    const float* __restrict__ x,const float* __restrict__ Wih,
    const float* __restrict__ Whh,const float* __restrict__ bih,
    const float* __restrict__ bhh)
{
    extern __shared__ char sm[];
    const int tid=threadIdx.x, eg=tid&3, gg=tid>>2;
    const int b0=blockIdx.x*32;

    for(int idx=tid;idx<4352;idx+=128){            // weights [kc17][s8][gg32]
        int kc=idx>>8,s=(idx>>5)&7,g=idx&31;
        int r=(s&3)*64+2*g+(s>>2);
        const float* src = (kc==0)? Wih+r*4 : Whh+r*64+(kc-1)*4;
        *(float4*)(sm+kc*4096+s*512+g*16)=*(const float4*)src;
    }

    const uint32_t smb=s2u(sm);
    const uint32_t wb0=smb+gg*16;
    uint32_t xrd=smb+V_OFF+eg*32;
    uint32_t hs=smb+V_OFF+VBUF+(4+2*gg)*128+eg*32;
    uint32_t xs=smb+V_OFF+VBUF+tid*4;
    {   // init V0: h rows zero; x(0) transposed into rows 0..3
        float4 z=make_float4(0.f,0.f,0.f,0.f);
        uint32_t vi=smb+V_OFF+(4+2*gg)*128+eg*32;
        STS4(vi,0,z);STS4(vi,16,z);STS4(vi,128,z);STS4(vi,144,z);
    }
    const float* xp=0;
    if(tid<32){
        xp=x+(size_t)(b0+tid)*TT*4;
        float4 x0=*(const float4*)xp;
        uint32_t xi=smb+V_OFF+tid*4;
        STS1(xi,0,x0.x);STS1(xi,128,x0.y);STS1(xi,256,x0.z);STS1(xi,384,x0.w);
    }
    float* gp=g_h1+(size_t)blockIdx.x*TT*2048+2*gg*32+eg*8;

    float bias[8];
#pragma unroll
    for(int s=0;s<8;s++){int r=(s&3)*64+2*gg+(s>>2);bias[s]=bih[r]+bhh[r];}
    float cc[2][8], hv[2][8];
#pragma unroll
    for(int u=0;u<2;u++)
#pragma unroll
        for(int e=0;e<8;e++)cc[u][e]=0.f;
    int xf=VBUF,hf=-VBUF;
    __syncthreads();

    for(int s=0;s<TT;s++){
        float4 px=make_float4(0.f,0.f,0.f,0.f);
        if(tid<32&&s+1<TT)px=*(const float4*)(xp+(size_t)(s+1)*4);

        u64 acc[8][4];
#pragma unroll
        for(int q=0;q<8;q++){u64 bp=pkss(bias[q]);
            acc[q][0]=bp;acc[q][1]=bp;acc[q][2]=bp;acc[q][3]=bp;}

        float p0,p1,p2,p3,q0,q1,q2,q3;
        uint32_t xb=xrd, wb=wb0;
        WLOADP(0);
#pragma unroll 4
        for(int kc=0;kc<17;kc++) PCHUNK;

        UPD(0);UPD(1);
        float4 t;
        t=make_float4(hv[0][0],hv[0][1],hv[0][2],hv[0][3]);STS4(hs,0,t);  *(float4*)(gp)   =t;
        t=make_float4(hv[0][4],hv[0][5],hv[0][6],hv[0][7]);STS4(hs,16,t); *(float4*)(gp+4) =t;
        t=make_float4(hv[1][0],hv[1][1],hv[1][2],hv[1][3]);STS4(hs,128,t);*(float4*)(gp+32)=t;
        t=make_float4(hv[1][4],hv[1][5],hv[1][6],hv[1][7]);STS4(hs,144,t);*(float4*)(gp+36)=t;
        gp+=2048;
        if(tid<32){STS1(xs,0,px.x);STS1(xs,128,px.y);STS1(xs,256,px.z);STS1(xs,384,px.w);}
        __syncthreads();
        xrd+=xf;xf=-xf; hs+=hf;xs+=hf;hf=-hf;
    }
}

// ---------------------------------------------------------------------------
extern "C" void kernel_launch(void* const* d_in, const int* in_sizes, int n_in,
                              void* d_out, int out_size)
{
    const float* x    =(const float*)d_in[0];
    const float* Wih0 =(const float*)d_in[1];
    const float* Whh0 =(const float*)d_in[2];
    const float* bih0 =(const float*)d_in[3];
    const float* bhh0 =(const float*)d_in[4];
    const float* Wih1 =(const float*)d_in[5];
    const float* Whh1 =(const float*)d_in[6];
    const float* bih1 =(const float*)d_in[7];
    const float* bhh1 =(const float*)d_in[8];
    const float* Wfc  =(const float*)d_in[9];
    const float* bfc  =(const float*)d_in[10];
    float* out=(float*)d_out;

    cudaFuncSetAttribute(lstm_l0,cudaFuncAttributeMaxDynamicSharedMemorySize,SM_TOTAL);
    cudaFuncSetAttribute(lstm_l1,cudaFuncAttributeMaxDynamicSharedMemorySize,SM_TOTAL);
    lstm_l0<<<128,128,SM_TOTAL>>>(x,Wih0,Whh0,bih0,bhh0);
    lstm_l1<<<128,128,SM_TOTAL>>>(Wih1,Whh1,bih1,bhh1,Wfc,bfc,out);
}

// round 10
// speedup vs baseline: 1.1945x; 1.0039x over previous
#include <cuda_runtime.h>
#include <cstdint>

// 2-layer LSTM (B=4096,T=256,D=4,H=64)+FC, fp32.
// R10: K-split 8gx8e tile. 256 thr/CTA (2 warps/SMSP): set A = K-chunks
// 0..15, set B = 16..31; partial accs exchanged via smem ([part][tid],
// conflict-free), update split by unit (A: unit0, B: unit1). Same pipelined
// GEMM inner loop as R9 (w slot prefetched one ahead, p/q reg sets).

#define TT 256
#define V_OFF 131072
#define VBUF  16384
#define P_OFF 163840          // 32KB partial-exchange scratch
#define SM_TOTAL 196608

typedef unsigned long long u64;
__device__ float g_h1[(size_t)128 * TT * 2048];   // [blk][t][j64][e32]

static __device__ __forceinline__ u64 pkss(float f){u64 r;asm("mov.b64 %0,{%1,%1};":"=l"(r):"f"(f));return r;}
static __device__ __forceinline__ void up2(u64 v,float&a,float&b){asm("mov.b64 {%0,%1},%2;":"=f"(a),"=f"(b):"l"(v));}
static __device__ __forceinline__ u64 f2(u64 a,u64 b,u64 c){u64 d;asm("fma.rn.f32x2 %0,%1,%2,%3;":"=l"(d):"l"(a),"l"(b),"l"(c));return d;}
static __device__ __forceinline__ u64 a2(u64 a,u64 b){u64 d;asm("add.rn.f32x2 %0,%1,%2;":"=l"(d):"l"(a),"l"(b));return d;}
static __device__ __forceinline__ float tanha(float x){float r;asm("tanh.approx.f32 %0,%1;":"=f"(r):"f"(x));return r;}
static __device__ __forceinline__ float sigt(float x){return fmaf(0.5f,tanha(0.5f*x),0.5f);}
static __device__ __forceinline__ uint32_t s2u(const void*p){uint32_t a;
    asm("{.reg .u64 t;cvta.to.shared.u64 t,%1;cvt.u32.u64 %0,t;}":"=r"(a):"l"(p));return a;}

#define XL2(d0,d1,IMM) asm volatile("ld.shared.v2.u64 {%0,%1},[%2+%3];" \
    :"=l"(d0),"=l"(d1):"r"(xb),"n"(IMM))
#define STS4(A,IMM,V) asm volatile("st.shared.v4.f32 [%0+%1],{%2,%3,%4,%5};" \
    ::"r"(A),"n"(IMM),"f"((V).x),"f"((V).y),"f"((V).z),"f"((V).w))
#define STS1(A,IMM,V) asm volatile("st.shared.f32 [%0+%1],%2;"::"r"(A),"n"(IMM),"f"(V))
#define WLOADP(IMM) asm volatile("ld.shared.v4.f32 {%0,%1,%2,%3},[%4+%5];" \
    :"=f"(p0),"=f"(p1),"=f"(p2),"=f"(p3):"r"(wb),"n"(IMM))
#define WLOADQ(IMM) asm volatile("ld.shared.v4.f32 {%0,%1,%2,%3},[%4+%5];" \
    :"=f"(q0),"=f"(q1),"=f"(q2),"=f"(q3):"r"(wb),"n"(IMM))

#define SLOTF(S,W) do{ u64 ws; \
  ws=pkss(W##0);acc[S][0]=f2(ws,x00,acc[S][0]);acc[S][1]=f2(ws,x01,acc[S][1]); \
               acc[S][2]=f2(ws,x02,acc[S][2]);acc[S][3]=f2(ws,x03,acc[S][3]); \
  ws=pkss(W##1);acc[S][0]=f2(ws,x10,acc[S][0]);acc[S][1]=f2(ws,x11,acc[S][1]); \
               acc[S][2]=f2(ws,x12,acc[S][2]);acc[S][3]=f2(ws,x13,acc[S][3]); \
  ws=pkss(W##2);acc[S][0]=f2(ws,x20,acc[S][0]);acc[S][1]=f2(ws,x21,acc[S][1]); \
               acc[S][2]=f2(ws,x22,acc[S][2]);acc[S][3]=f2(ws,x23,acc[S][3]); \
  ws=pkss(W##3);acc[S][0]=f2(ws,x30,acc[S][0]);acc[S][1]=f2(ws,x31,acc[S][1]); \
               acc[S][2]=f2(ws,x32,acc[S][2]);acc[S][3]=f2(ws,x33,acc[S][3]); \
}while(0)

#define PCHUNK do{ \
  u64 x00,x01,x02,x03,x10,x11,x12,x13,x20,x21,x22,x23,x30,x31,x32,x33; \
  XL2(x00,x01,0);  XL2(x02,x03,16); XL2(x10,x11,128);XL2(x12,x13,144); \
  XL2(x20,x21,256);XL2(x22,x23,272);XL2(x30,x31,384);XL2(x32,x33,400); \
  WLOADQ(512);  SLOTF(0,p); \
  WLOADP(1024); SLOTF(1,q); \
  WLOADQ(1536); SLOTF(2,p); \
  WLOADP(2048); SLOTF(3,q); \
  WLOADQ(2560); SLOTF(4,p); \
  WLOADP(3072); SLOTF(5,q); \
  WLOADQ(3584); SLOTF(6,p); \
  WLOADP(4096); SLOTF(7,q); \
  wb+=4096; xb+=512; \
}while(0)

// store my other-unit partials (slots SB..SB+3) to [part16][tid]*16B scratch
#define PST(SB,A_) do{ \
  asm volatile("st.shared.v2.u64 [%0+0],{%1,%2};"::"r"(A_),"l"(acc[SB][0]),"l"(acc[SB][1])); \
  asm volatile("st.shared.v2.u64 [%0+2048],{%1,%2};"::"r"(A_),"l"(acc[SB][2]),"l"(acc[SB][3])); \
  asm volatile("st.shared.v2.u64 [%0+4096],{%1,%2};"::"r"(A_),"l"(acc[(SB)+1][0]),"l"(acc[(SB)+1][1])); \
  asm volatile("st.shared.v2.u64 [%0+6144],{%1,%2};"::"r"(A_),"l"(acc[(SB)+1][2]),"l"(acc[(SB)+1][3])); \
  asm volatile("st.shared.v2.u64 [%0+8192],{%1,%2};"::"r"(A_),"l"(acc[(SB)+2][0]),"l"(acc[(SB)+2][1])); \
  asm volatile("st.shared.v2.u64 [%0+10240],{%1,%2};"::"r"(A_),"l"(acc[(SB)+2][2]),"l"(acc[(SB)+2][3])); \
  asm volatile("st.shared.v2.u64 [%0+12288],{%1,%2};"::"r"(A_),"l"(acc[(SB)+3][0]),"l"(acc[(SB)+3][1])); \
  asm volatile("st.shared.v2.u64 [%0+14336],{%1,%2};"::"r"(A_),"l"(acc[(SB)+3][2]),"l"(acc[(SB)+3][3])); \
}while(0)
// load peer's partials for my unit (slots SB..SB+3) and add
#define PLA(SB,A_) do{ u64 t0,t1; \
  asm volatile("ld.shared.v2.u64 {%0,%1},[%2+0];":"=l"(t0),"=l"(t1):"r"(A_)); \
  acc[SB][0]=a2(acc[SB][0],t0); acc[SB][1]=a2(acc[SB][1],t1); \
  asm volatile("ld.shared.v2.u64 {%0,%1},[%2+2048];":"=l"(t0),"=l"(t1):"r"(A_)); \
  acc[SB][2]=a2(acc[SB][2],t0); acc[SB][3]=a2(acc[SB][3],t1); \
  asm volatile("ld.shared.v2.u64 {%0,%1},[%2+4096];":"=l"(t0),"=l"(t1):"r"(A_)); \
  acc[(SB)+1][0]=a2(acc[(SB)+1][0],t0); acc[(SB)+1][1]=a2(acc[(SB)+1][1],t1); \
  asm volatile("ld.shared.v2.u64 {%0,%1},[%2+6144];":"=l"(t0),"=l"(t1):"r"(A_)); \
  acc[(SB)+1][2]=a2(acc[(SB)+1][2],t0); acc[(SB)+1][3]=a2(acc[(SB)+1][3],t1); \
  asm volatile("ld.shared.v2.u64 {%0,%1},[%2+8192];":"=l"(t0),"=l"(t1):"r"(A_)); \
  acc[(SB)+2][0]=a2(acc[(SB)+2][0],t0); acc[(SB)+2][1]=a2(acc[(SB)+2][1],t1); \
  asm volatile("ld.shared.v2.u64 {%0,%1},[%2+10240];":"=l"(t0),"=l"(t1):"r"(A_)); \
  acc[(SB)+2][2]=a2(acc[(SB)+2][2],t0); acc[(SB)+2][3]=a2(acc[(SB)+2][3],t1); \
  asm volatile("ld.shared.v2.u64 {%0,%1},[%2+12288];":"=l"(t0),"=l"(t1):"r"(A_)); \
  acc[(SB)+3][0]=a2(acc[(SB)+3][0],t0); acc[(SB)+3][1]=a2(acc[(SB)+3][1],t1); \
  asm volatile("ld.shared.v2.u64 {%0,%1},[%2+14336];":"=l"(t0),"=l"(t1):"r"(A_)); \
  acc[(SB)+3][2]=a2(acc[(SB)+3][2],t0); acc[(SB)+3][3]=a2(acc[(SB)+3][3],t1); \
}while(0)

// update ONE unit (slots SB..SB+3) -> cc[8], hv[8]
#define UPD8(SB) do{ _Pragma("unroll") for(int p_=0;p_<4;p_++){ \
  float i0,i1,f0,f1,g0,g1,o0,o1; \
  up2(acc[SB][p_],i0,i1);      up2(acc[(SB)+1][p_],f0,f1); \
  up2(acc[(SB)+2][p_],g0,g1);  up2(acc[(SB)+3][p_],o0,o1); \
  cc[2*p_]  =sigt(f0)*cc[2*p_]  +sigt(i0)*tanha(g0); \
  cc[2*p_+1]=sigt(f1)*cc[2*p_+1]+sigt(i1)*tanha(g1); \
  hv[2*p_]  =sigt(o0)*tanha(cc[2*p_]); \
  hv[2*p_+1]=sigt(o1)*tanha(cc[2*p_+1]); }}while(0)

#define EXCHANGE_AND_UPDATE() do{ \
  if(st==0){ PST(4,pst_a); } else { PST(0,pst_a); } \
}while(0)

// ---------------------------------------------------------------------------
__global__ void __launch_bounds__(256,1) lstm_l1(
    const float* __restrict__ Wih,const float* __restrict__ Whh,
    const float* __restrict__ bih,const float* __restrict__ bhh,
    const float* __restrict__ Wfc,const float* __restrict__ bfc,
    float* __restrict__ out)
{
    extern __shared__ char sm[];
    const int tid=threadIdx.x, st=tid>>7, t=tid&127, eg=t&3, gg=t>>2;
    const int b0=blockIdx.x*32;

    for(int idx=tid;idx<8192;idx+=256){            // weights [kc32][s8][gg32]
        int kc=idx>>8,s=(idx>>5)&7,g=idx&31;
        int r=(s&3)*64+2*g+(s>>2), k=kc*4;
        const float* src = (k<64)? Wih+r*64+k : Whh+r*64+(k-64);
        *(float4*)(sm+kc*4096+s*512+g*16)=*(const float4*)src;
    }

    const uint32_t smb=s2u(sm);
    const uint32_t wb0=smb+gg*16+st*65536;          // set B: chunks 16..31
    uint32_t xrd=smb+V_OFF+eg*32+st*8192;           // set B: v rows 64..127
    uint32_t hs=smb+V_OFF+VBUF+(64+2*gg+st)*128+eg*32;
    uint32_t ps=smb+V_OFF+VBUF+(2*gg+st)*128+eg*32;
    const uint32_t pst_a=smb+P_OFF+st*16384+t*16;
    const uint32_t pld_a=smb+P_OFF+(1-st)*16384+t*16;

    const float* h1p=g_h1+(size_t)blockIdx.x*TT*2048+(2*gg+st)*32+eg*8;
    {   // V0: row (2gg+st) <- h1[t=0]; row (64+2gg+st) <- 0
        float4 a=*(const float4*)h1p, b4=*(const float4*)(h1p+4);
        uint32_t vi=smb+V_OFF+(2*gg+st)*128+eg*32;
        STS4(vi,0,a); STS4(vi,16,b4);
        float4 z=make_float4(0.f,0.f,0.f,0.f);
        STS4(vi,8192,z); STS4(vi,8208,z);
    }
    h1p+=2048;

    float bias[8];
#pragma unroll
    for(int s=0;s<8;s++){
        int r=(s&3)*64+2*gg+(s>>2);
        bias[s]=(st==0)? (bih[r]+bhh[r]) : 0.f;
    }
    float cc[8], hv[8];
#pragma unroll
    for(int e=0;e<8;e++)cc[e]=0.f;
    int xf=VBUF,hf=-VBUF;
    __syncthreads();

    for(int s=0;s<TT;s++){
        float4 pA,pB;
        if(s+1<TT){pA=*(const float4*)h1p; pB=*(const float4*)(h1p+4);}
        else {pA=pB=make_float4(0.f,0.f,0.f,0.f);}
        h1p+=2048;

        u64 acc[8][4];
#pragma unroll
        for(int q=0;q<8;q++){u64 bp=pkss(bias[q]);
            acc[q][0]=bp;acc[q][1]=bp;acc[q][2]=bp;acc[q][3]=bp;}

        float p0,p1,p2,p3,q0,q1,q2,q3;
        uint32_t xb=xrd, wb=wb0;
        WLOADP(0);
#pragma unroll 4
        for(int kc=0;kc<16;kc++) PCHUNK;

        if(st==0){ PST(4,pst_a); } else { PST(0,pst_a); }
        STS4(ps,0,pA); STS4(ps,16,pB);
        __syncthreads();                            // partials visible
        if(st==0){ PLA(0,pld_a); UPD8(0); }
        else     { PLA(4,pld_a); UPD8(4); }
        {
            float4 h4=make_float4(hv[0],hv[1],hv[2],hv[3]);
            float4 h5=make_float4(hv[4],hv[5],hv[6],hv[7]);
            STS4(hs,0,h4); STS4(hs,16,h5);
        }
        __syncthreads();                            // v[next] complete
        xrd+=xf;xf=-xf; hs+=hf;ps+=hf;hf=-hf;
    }

    // fused FC: thread owns unit j=2gg+st
    {
        float wf=Wfc[2*gg+st];
        float4 t0=make_float4(hv[0]*wf,hv[1]*wf,hv[2]*wf,hv[3]*wf);
        float4 t1=make_float4(hv[4]*wf,hv[5]*wf,hv[6]*wf,hv[7]*wf);
        uint32_t pb=smb+V_OFF+(2*gg+st)*128+eg*32;
        STS4(pb,0,t0); STS4(pb,16,t1);
        __syncthreads();
        if(tid<32){
            float v=bfc[0];
#pragma unroll
            for(int g=0;g<64;g++) v+=*(const float*)(sm+V_OFF+g*128+tid*4);
            out[b0+tid]=v;
        }
    }
}

// ---------------------------------------------------------------------------
// Layer 0: v rows 0..3 = x (chunk 0), rows 4..67 = h (chunks 1..16).
// Set A: chunks 0..8 (9), set B: chunks 9..16 (8).
__global__ void __launch_bounds__(256,1) lstm_l0(
    const float* __restrict__ x,const float* __restrict__ Wih,
    const float* __restrict__ Whh,const float* __restrict__ bih,
    const float* __restrict__ bhh)
{
    extern __shared__ char sm[];
    const int tid=threadIdx.x, st=tid>>7, t=tid&127, eg=t&3, gg=t>>2;
    const int b0=blockIdx.x*32;

    for(int idx=tid;idx<4352;idx+=256){            // weights [kc17][s8][gg32]
        int kc=idx>>8,s=(idx>>5)&7,g=idx&31;
        int r=(s&3)*64+2*g+(s>>2);
        const float* src = (kc==0)? Wih+r*4 : Whh+r*64+(kc-1)*4;
        *(float4*)(sm+kc*4096+s*512+g*16)=*(const float4*)src;
    }

    const uint32_t smb=s2u(sm);
    const uint32_t wb0=smb+gg*16+st*36864;          // set B starts chunk 9
    uint32_t xrd=smb+V_OFF+eg*32+st*4608;           // set B rows 36..67
    uint32_t hs=smb+V_OFF+VBUF+(4+2*gg+st)*128+eg*32;
    uint32_t xs=smb+V_OFF+VBUF+(tid&127)*4;         // only tid<32 uses
    const uint32_t pst_a=smb+P_OFF+st*16384+t*16;
    const uint32_t pld_a=smb+P_OFF+(1-st)*16384+t*16;
    const int nch = 9 - st;

    {   // V0: h row (4+2gg+st) <- 0
        float4 z=make_float4(0.f,0.f,0.f,0.f);
        uint32_t vi=smb+V_OFF+(4+2*gg+st)*128+eg*32;
        STS4(vi,0,z); STS4(vi,16,z);
    }
    const float* xp=0;
    if(tid<32){
        xp=x+(size_t)(b0+tid)*TT*4;
        float4 x0=*(const float4*)xp;
        uint32_t xi=smb+V_OFF+tid*4;
        STS1(xi,0,x0.x);STS1(xi,128,x0.y);STS1(xi,256,x0.z);STS1(xi,384,x0.w);
    }
    float* gp=g_h1+(size_t)blockIdx.x*TT*2048+(2*gg+st)*32+eg*8;

    float bias[8];
#pragma unroll
    for(int s=0;s<8;s++){
        int r=(s&3)*64+2*gg+(s>>2);
        bias[s]=(st==0)? (bih[r]+bhh[r]) : 0.f;
    }
    float cc[8], hv[8];
#pragma unroll
    for(int e=0;e<8;e++)cc[e]=0.f;
    int xf=VBUF,hf=-VBUF;
    __syncthreads();

    for(int s=0;s<TT;s++){
        float4 px=make_float4(0.f,0.f,0.f,0.f);
        if(tid<32&&s+1<TT)px=*(const float4*)(xp+(size_t)(s+1)*4);

        u64 acc[8][4];
#pragma unroll
        for(int q=0;q<8;q++){u64 bp=pkss(bias[q]);
            acc[q][0]=bp;acc[q][1]=bp;acc[q][2]=bp;acc[q][3]=bp;}

        float p0,p1,p2,p3,q0,q1,q2,q3;
        uint32_t xb=xrd, wb=wb0;
        WLOADP(0);
#pragma unroll 3
        for(int kc=0;kc<nch;kc++) PCHUNK;

        if(st==0){ PST(4,pst_a); } else { PST(0,pst_a); }
        if(tid<32){STS1(xs,0,px.x);STS1(xs,128,px.y);STS1(xs,256,px.z);STS1(xs,384,px.w);}
        __syncthreads();
        if(st==0){ PLA(0,pld_a); UPD8(0); }
        else     { PLA(4,pld_a); UPD8(4); }
        {
            float4 h4=make_float4(hv[0],hv[1],hv[2],hv[3]);
            float4 h5=make_float4(hv[4],hv[5],hv[6],hv[7]);
            STS4(hs,0,h4); STS4(hs,16,h5);
            *(float4*)(gp)  =h4;
            *(float4*)(gp+4)=h5;
        }
        gp+=2048;
        __syncthreads();
        xrd+=xf;xf=-xf; hs+=hf;xs+=hf;hf=-hf;
    }
}

// ---------------------------------------------------------------------------
extern "C" void kernel_launch(void* const* d_in, const int* in_sizes, int n_in,
                              void* d_out, int out_size)
{
    const float* x    =(const float*)d_in[0];
    const float* Wih0 =(const float*)d_in[1];
    const float* Whh0 =(const float*)d_in[2];
    const float* bih0 =(const float*)d_in[3];
    const float* bhh0 =(const float*)d_in[4];
    const float* Wih1 =(const float*)d_in[5];
    const float* Whh1 =(const float*)d_in[6];
    const float* bih1 =(const float*)d_in[7];
    const float* bhh1 =(const float*)d_in[8];
    const float* Wfc  =(const float*)d_in[9];
    const float* bfc  =(const float*)d_in[10];
    float* out=(float*)d_out;

    cudaFuncSetAttribute(lstm_l0,cudaFuncAttributeMaxDynamicSharedMemorySize,SM_TOTAL);
    cudaFuncSetAttribute(lstm_l1,cudaFuncAttributeMaxDynamicSharedMemorySize,SM_TOTAL);
    lstm_l0<<<128,256,SM_TOTAL>>>(x,Wih0,Whh0,bih0,bhh0);
    lstm_l1<<<128,256,SM_TOTAL>>>(Wih1,Whh1,bih1,bhh1,Wfc,bfc,out);
}